// round 5
// baseline (speedup 1.0000x reference)
#include <cuda_runtime.h>
#include <math.h>

#define L_LAYERS 2
#define NNEI 120
#define ED 64
#define HD 128
#define FDIM 384          // 3*HD
#define NW 32
#define NTHREADS 1024
#define SCALING 0.08838834764831845f   // HD^-0.5
#define LN_EPS 1e-5f

// shared memory layout (floats)
#define OFF_SX   0                         // 120*64   = 7680
#define OFF_SQ   7680                      // 120*128  = 15360 (q, later o)
#define OFF_SK   23040                     // 120*128  = 15360 (k, row-major, XOR-swizzled)
#define OFF_SV   38400                     // 120*128  = 15360
#define OFF_BUF  53760                     // 3840: weight staging (<=2048) / aw (32*120)
#define OFF_R    57600                     // 120*3
#define OFF_MASK 57960                     // 120
#define SMEM_FLOATS 58080                  // 232320 B <= 232448 limit

typedef unsigned long long u64;

__device__ __forceinline__ u64 ffma2(u64 a, u64 b, u64 c) {
    u64 d; asm("fma.rn.f32x2 %0, %1, %2, %3;" : "=l"(d) : "l"(a), "l"(b), "l"(c));
    return d;
}
__device__ __forceinline__ u64 pack2(float lo, float hi) {
    u64 d; asm("mov.b64 %0, {%1, %2};" : "=l"(d) : "f"(lo), "f"(hi));
    return d;
}
__device__ __forceinline__ float hsum2(u64 v) {
    float lo, hi; asm("mov.b64 {%0, %1}, %2;" : "=f"(lo), "=f"(hi) : "l"(v));
    return lo + hi;
}

__device__ __forceinline__ float warp_sum(float v) {
    #pragma unroll
    for (int o = 16; o; o >>= 1) v += __shfl_xor_sync(0xffffffffu, v, o);
    return v;
}
__device__ __forceinline__ float warp_max(float v) {
    #pragma unroll
    for (int o = 16; o; o >>= 1) v = fmaxf(v, __shfl_xor_sync(0xffffffffu, v, o));
    return v;
}

__global__ __launch_bounds__(NTHREADS, 1)
void nwa_kernel(const float* __restrict__ G,
                const int* __restrict__ maskp,          // bool arrives as int32
                const float* __restrict__ rp,
                const float* __restrict__ in_w, const float* __restrict__ in_b,
                const float* __restrict__ out_w, const float* __restrict__ out_b,
                const float* __restrict__ ln_g, const float* __restrict__ ln_b,
                float* __restrict__ out)
{
    extern __shared__ float sm[];
    float* sx    = sm + OFF_SX;
    float* sq    = sm + OFF_SQ;
    float* sk    = sm + OFF_SK;
    float* sv    = sm + OFF_SV;
    float* sbuf  = sm + OFF_BUF;
    float* sr    = sm + OFF_R;
    float* smask = sm + OFF_MASK;
    float4* sx4  = (float4*)sx;

    const int b = blockIdx.x;
    const int tid = threadIdx.x;
    const int w = tid >> 5;
    const int lane = tid & 31;

    // ---- load per-batch inputs ----
    {
        const float4* Gx = (const float4*)(G + (size_t)b * NNEI * ED);
        for (int i = tid; i < NNEI * ED / 4; i += NTHREADS) sx4[i] = Gx[i];
        const float* rb = rp + (size_t)b * NNEI * 3;
        for (int i = tid; i < NNEI * 3; i += NTHREADS) sr[i] = rb[i];
        if (tid < NNEI) smask[tid] = maskp[(size_t)b * NNEI + tid] ? 1.0f : 0.0f;
    }
    __syncthreads();

    for (int l = 0; l < L_LAYERS; l++) {
        // ========== Phase A: qkv = x @ in_w + in_b  (packed over e) ==========
        const float* Wl = in_w + (size_t)l * ED * FDIM;
        for (int fc = 0; fc < FDIM / 32; fc++) {
            // stage weight chunk pair-interleaved: sbuf[(e>>1)*64 + 2*j + (e&1)]
            for (int idx = tid; idx < ED * 32; idx += NTHREADS) {
                int e = idx >> 5, j = idx & 31;
                sbuf[(e >> 1) * 64 + 2 * j + (e & 1)] = Wl[e * FDIM + fc * 32 + j];
            }
            __syncthreads();
            u64 acc[4] = {0ull, 0ull, 0ull, 0ull};
            #pragma unroll 4
            for (int k4 = 0; k4 < 16; k4++) {          // e = 4*k4 .. 4*k4+3
                u64 wa = *(const u64*)(sbuf + (2 * k4) * 64 + 2 * lane);
                u64 wb = *(const u64*)(sbuf + (2 * k4 + 1) * 64 + 2 * lane);
                #pragma unroll
                for (int i = 0; i < 4; i++) {
                    int n = w + 32 * i;
                    if (n < NNEI) {
                        ulonglong2 xq = *(const ulonglong2*)(sx + n * ED + 4 * k4);
                        acc[i] = ffma2(xq.x, wa, acc[i]);
                        acc[i] = ffma2(xq.y, wb, acc[i]);
                    }
                }
            }
            int f = fc * 32 + lane;
            float bv = in_b[l * FDIM + f];
            #pragma unroll
            for (int i = 0; i < 4; i++) {
                int n = w + 32 * i;
                if (n < NNEI) {
                    float v = hsum2(acc[i]) + bv;
                    if (f < HD)            sq[n * HD + f] = v;
                    else if (f < 2 * HD) { int hk = f - HD;
                                           sk[n * HD + (hk ^ ((4 * n) & 127))] = v; }
                    else                   sv[n * HD + (f - 2 * HD)] = v;
                }
            }
            __syncthreads();
        }

        // ========== Phase B: l2norm rows of q, k, v (k swizzle is a permutation) ==========
        for (int task = w; task < 3 * NNEI; task += NW) {
            int type = task / NNEI;   // 0=q, 1=k, 2=v
            int n = task - type * NNEI;
            float* base = (type == 0 ? sq : (type == 1 ? sk : sv)) + n * HD;
            float4 vv = ((float4*)base)[lane];
            float s = vv.x * vv.x + vv.y * vv.y + vv.z * vv.z + vv.w * vv.w;
            s = warp_sum(s);
            float sc = 1.0f / fmaxf(sqrtf(s), 1e-12f);
            if (type == 0) sc *= SCALING;
            vv.x *= sc; vv.y *= sc; vv.z *= sc; vv.w *= sc;
            ((float4*)base)[lane] = vv;
        }
        __syncthreads();

        // ========== Phase C+E: attention, 2 rows/warp, 2 passes ==========
        float* awrow = sbuf + w * NNEI;
        // per-j clamped k row + its swizzle rotation
        int mrow[4], rot[4];
        #pragma unroll
        for (int j = 0; j < 4; j++) {
            int m = lane + 32 * j;
            mrow[j] = (m < NNEI) ? m : 0;
            rot[j] = (4 * mrow[j]) & 127;
        }
        for (int pass = 0; pass < 2; pass++) {
            int n0 = pass * 64 + 2 * w;
            if (n0 < NNEI) {
                int n1 = n0 + 1;
                // --- QK^T packed over h, shared k loads across 2 rows ---
                u64 acc[2][4];
                #pragma unroll
                for (int j = 0; j < 4; j++) { acc[0][j] = 0ull; acc[1][j] = 0ull; }
                #pragma unroll 4
                for (int h = 0; h < HD; h += 4) {
                    ulonglong2 q0 = *(const ulonglong2*)(sq + n0 * HD + h);
                    ulonglong2 q1 = *(const ulonglong2*)(sq + n1 * HD + h);
                    #pragma unroll
                    for (int j = 0; j < 4; j++) {
                        ulonglong2 k4 = *(const ulonglong2*)(sk + mrow[j] * HD + (h ^ rot[j]));
                        acc[0][j] = ffma2(q0.x, k4.x, acc[0][j]);
                        acc[0][j] = ffma2(q0.y, k4.y, acc[0][j]);
                        acc[1][j] = ffma2(q1.x, k4.x, acc[1][j]);
                        acc[1][j] = ffma2(q1.y, k4.y, acc[1][j]);
                    }
                }
                #pragma unroll
                for (int r = 0; r < 2; r++) {
                    int n = n0 + r;
                    // --- softmax + mask + angle ---
                    float lg[4]; float mx = -1e30f;
                    #pragma unroll
                    for (int j = 0; j < 4; j++) {
                        int m = lane + 32 * j;
                        float s = hsum2(acc[r][j]);
                        bool ok = (m < NNEI) && (smask[m] > 0.5f);
                        lg[j] = ok ? s : -1e30f;
                        mx = fmaxf(mx, lg[j]);
                    }
                    mx = warp_max(mx);
                    float ex[4], ssum = 0.f;
                    #pragma unroll
                    for (int j = 0; j < 4; j++) { ex[j] = __expf(lg[j] - mx); ssum += ex[j]; }
                    ssum = warp_sum(ssum);
                    float inv = 1.0f / ssum;
                    float qm = smask[n];
                    float rn0 = sr[n * 3], rn1 = sr[n * 3 + 1], rn2 = sr[n * 3 + 2];
                    #pragma unroll
                    for (int j = 0; j < 4; j++) {
                        int m = lane + 32 * j;
                        if (m < NNEI) {
                            float ang = rn0 * sr[m * 3] + rn1 * sr[m * 3 + 1] + rn2 * sr[m * 3 + 2];
                            awrow[m] = ex[j] * inv * qm * ang;
                        }
                    }
                    __syncwarp();
                    // --- AV: o[n][4*lane..+3], packed over h' ---
                    u64 o2a = 0ull, o2b = 0ull;
                    #pragma unroll 2
                    for (int m = 0; m < NNEI; m += 2) {
                        float2 p = *(const float2*)(awrow + m);
                        u64 pp0 = pack2(p.x, p.x);
                        u64 pp1 = pack2(p.y, p.y);
                        ulonglong2 v0 = *(const ulonglong2*)(sv + m * HD + 4 * lane);
                        ulonglong2 v1 = *(const ulonglong2*)(sv + (m + 1) * HD + 4 * lane);
                        o2a = ffma2(pp0, v0.x, o2a); o2b = ffma2(pp0, v0.y, o2b);
                        o2a = ffma2(pp1, v1.x, o2a); o2b = ffma2(pp1, v1.y, o2b);
                    }
                    ulonglong2 ov; ov.x = o2a; ov.y = o2b;
                    *(ulonglong2*)(sq + n * HD + 4 * lane) = ov;   // overwrite q with o
                    __syncwarp();
                }
            }
        }
        __syncthreads();

        // ========== Phase F: x = LN(residual + o @ out_w + out_b)  (packed over h) ==========
        const float* Ow = out_w + (size_t)l * HD * ED;
        u64 accF[4][2];
        #pragma unroll
        for (int i = 0; i < 4; i++) { accF[i][0] = 0ull; accF[i][1] = 0ull; }
        for (int hc = 0; hc < 4; hc++) {
            // stage 32 h x 64 e chunk, pair-interleaved over h:
            // sbuf[(hl>>1)*128 + 2*e + (hl&1)]
            for (int idx = tid; idx < 32 * ED; idx += NTHREADS) {
                int hl = idx >> 6, e = idx & 63;
                sbuf[(hl >> 1) * 128 + 2 * e + (hl & 1)] = Ow[(hc * 32 + hl) * ED + e];
            }
            __syncthreads();
            #pragma unroll 4
            for (int h2 = 0; h2 < 16; h2++) {
                u64 w0 = *(const u64*)(sbuf + h2 * 128 + 2 * lane);
                u64 w1 = *(const u64*)(sbuf + h2 * 128 + 64 + 2 * lane);
                #pragma unroll
                for (int i = 0; i < 4; i++) {
                    int n = w + 32 * i;
                    if (n < NNEI) {
                        u64 op = *(const u64*)(sq + n * HD + hc * 32 + 2 * h2);
                        accF[i][0] = ffma2(op, w0, accF[i][0]);
                        accF[i][1] = ffma2(op, w1, accF[i][1]);
                    }
                }
            }
            __syncthreads();
        }
        {
            float ob0 = out_b[l * ED + lane],      ob1 = out_b[l * ED + 32 + lane];
            float g0  = ln_g[l * ED + lane],       g1  = ln_g[l * ED + 32 + lane];
            float bb0 = ln_b[l * ED + lane],       bb1 = ln_b[l * ED + 32 + lane];
            #pragma unroll
            for (int i = 0; i < 4; i++) {
                int n = w + 32 * i;
                if (n < NNEI) {
                    float x0 = sx[n * ED + lane]      + hsum2(accF[i][0]) + ob0;
                    float x1 = sx[n * ED + 32 + lane] + hsum2(accF[i][1]) + ob1;
                    float mu = warp_sum(x0 + x1) * (1.0f / 64.0f);
                    float d0 = x0 - mu, d1 = x1 - mu;
                    float var = warp_sum(d0 * d0 + d1 * d1) * (1.0f / 64.0f);
                    float rs = rsqrtf(var + LN_EPS);
                    sx[n * ED + lane]      = d0 * rs * g0 + bb0;
                    sx[n * ED + 32 + lane] = d1 * rs * g1 + bb1;
                }
            }
        }
        __syncthreads();
    }

    // ---- write output ----
    float4* outp = (float4*)(out + (size_t)b * NNEI * ED);
    for (int i = tid; i < NNEI * ED / 4; i += NTHREADS) outp[i] = sx4[i];
}

extern "C" void kernel_launch(void* const* d_in, const int* in_sizes, int n_in,
                              void* d_out, int out_size) {
    const float* G     = (const float*)d_in[0];
    const int* mk      = (const int*)d_in[1];      // bool -> int32 per harness dtypes
    const float* r     = (const float*)d_in[2];
    const float* in_w  = (const float*)d_in[3];
    const float* in_b  = (const float*)d_in[4];
    const float* out_w = (const float*)d_in[5];
    const float* out_b = (const float*)d_in[6];
    const float* ln_g  = (const float*)d_in[7];
    const float* ln_b  = (const float*)d_in[8];
    float* out         = (float*)d_out;

    int B = in_sizes[0] / (NNEI * ED);

    cudaFuncSetAttribute(nwa_kernel, cudaFuncAttributeMaxDynamicSharedMemorySize,
                         SMEM_FLOATS * sizeof(float));
    nwa_kernel<<<B, NTHREADS, SMEM_FLOATS * sizeof(float)>>>(
        G, mk, r, in_w, in_b, out_w, out_b, ln_g, ln_b, out);
}

// round 6
// speedup vs baseline: 1.1771x; 1.1771x over previous
#include <cuda_runtime.h>
#include <math.h>

#define L_LAYERS 2
#define NNEI 120
#define ED 64
#define HD 128
#define FDIM 384          // 3*HD
#define NW 32
#define NTHREADS 1024
#define SCALING 0.08838834764831845f   // HD^-0.5
#define LN_EPS 1e-5f

// shared memory layout (floats)
#define OFF_SX   0                         // 120*64   = 7680
#define OFF_SQ   7680                      // 120*128  = 15360 (q, later o)
#define OFF_SK   23040                     // 120*128  = 15360 (k, row-major, XOR-swizzled)
#define OFF_SV   38400                     // 120*128  = 15360
#define OFF_BUF  53760                     // 3840: weight staging
#define OFF_R    57600                     // 120*3
#define OFF_MASK 57960                     // 120
#define SMEM_FLOATS 58080                  // 232320 B <= 232448 limit

typedef unsigned long long u64;

__device__ __forceinline__ u64 ffma2(u64 a, u64 b, u64 c) {
    u64 d; asm("fma.rn.f32x2 %0, %1, %2, %3;" : "=l"(d) : "l"(a), "l"(b), "l"(c));
    return d;
}
__device__ __forceinline__ u64 pack2(float lo, float hi) {
    u64 d; asm("mov.b64 %0, {%1, %2};" : "=l"(d) : "f"(lo), "f"(hi));
    return d;
}
__device__ __forceinline__ float hsum2(u64 v) {
    float lo, hi; asm("mov.b64 {%0, %1}, %2;" : "=f"(lo), "=f"(hi) : "l"(v));
    return lo + hi;
}

__device__ __forceinline__ float warp_sum(float v) {
    #pragma unroll
    for (int o = 16; o; o >>= 1) v += __shfl_xor_sync(0xffffffffu, v, o);
    return v;
}
__device__ __forceinline__ float warp_max(float v) {
    #pragma unroll
    for (int o = 16; o; o >>= 1) v = fmaxf(v, __shfl_xor_sync(0xffffffffu, v, o));
    return v;
}

__global__ __launch_bounds__(NTHREADS, 1)
void nwa_kernel(const float* __restrict__ G,
                const int* __restrict__ maskp,          // bool arrives as int32
                const float* __restrict__ rp,
                const float* __restrict__ in_w, const float* __restrict__ in_b,
                const float* __restrict__ out_w, const float* __restrict__ out_b,
                const float* __restrict__ ln_g, const float* __restrict__ ln_b,
                float* __restrict__ out)
{
    extern __shared__ float sm[];
    float* sx    = sm + OFF_SX;
    float* sq    = sm + OFF_SQ;
    float* sk    = sm + OFF_SK;
    float* sv    = sm + OFF_SV;
    float* sbuf  = sm + OFF_BUF;
    float* sr    = sm + OFF_R;
    float* smask = sm + OFF_MASK;
    float4* sx4  = (float4*)sx;

    const int b = blockIdx.x;
    const int tid = threadIdx.x;
    const int w = tid >> 5;
    const int lane = tid & 31;

    // ---- load per-batch inputs ----
    {
        const float4* Gx = (const float4*)(G + (size_t)b * NNEI * ED);
        for (int i = tid; i < NNEI * ED / 4; i += NTHREADS) sx4[i] = Gx[i];
        const float* rb = rp + (size_t)b * NNEI * 3;
        for (int i = tid; i < NNEI * 3; i += NTHREADS) sr[i] = rb[i];
        if (tid < NNEI) smask[tid] = maskp[(size_t)b * NNEI + tid] ? 1.0f : 0.0f;
    }
    __syncthreads();

    for (int l = 0; l < L_LAYERS; l++) {
        // ========== Phase A: qkv = x @ in_w + in_b  (packed over e) ==========
        const float* Wl = in_w + (size_t)l * ED * FDIM;
        for (int fc = 0; fc < FDIM / 32; fc++) {
            // stage weight chunk pair-interleaved: sbuf[(e>>1)*64 + 2*j + (e&1)]
            for (int idx = tid; idx < ED * 32; idx += NTHREADS) {
                int e = idx >> 5, j = idx & 31;
                sbuf[(e >> 1) * 64 + 2 * j + (e & 1)] = Wl[e * FDIM + fc * 32 + j];
            }
            __syncthreads();
            u64 acc[4] = {0ull, 0ull, 0ull, 0ull};
            #pragma unroll 4
            for (int k4 = 0; k4 < 16; k4++) {          // e = 4*k4 .. 4*k4+3
                u64 wa = *(const u64*)(sbuf + (2 * k4) * 64 + 2 * lane);
                u64 wb = *(const u64*)(sbuf + (2 * k4 + 1) * 64 + 2 * lane);
                #pragma unroll
                for (int i = 0; i < 4; i++) {
                    int n = w + 32 * i;
                    if (n < NNEI) {
                        ulonglong2 xq = *(const ulonglong2*)(sx + n * ED + 4 * k4);
                        acc[i] = ffma2(xq.x, wa, acc[i]);
                        acc[i] = ffma2(xq.y, wb, acc[i]);
                    }
                }
            }
            int f = fc * 32 + lane;
            float bv = in_b[l * FDIM + f];
            #pragma unroll
            for (int i = 0; i < 4; i++) {
                int n = w + 32 * i;
                if (n < NNEI) {
                    float v = hsum2(acc[i]) + bv;
                    if (f < HD)            sq[n * HD + f] = v;
                    else if (f < 2 * HD) { int hk = f - HD;
                                           sk[n * HD + (hk ^ ((4 * n) & 127))] = v; }
                    else                   sv[n * HD + (f - 2 * HD)] = v;
                }
            }
            __syncthreads();
        }

        // ========== Phase B: l2norm rows of q, k, v (k swizzle is a permutation) ==========
        for (int task = w; task < 3 * NNEI; task += NW) {
            int type = task / NNEI;   // 0=q, 1=k, 2=v
            int n = task - type * NNEI;
            float* base = (type == 0 ? sq : (type == 1 ? sk : sv)) + n * HD;
            float4 vv = ((float4*)base)[lane];
            float s = vv.x * vv.x + vv.y * vv.y + vv.z * vv.z + vv.w * vv.w;
            s = warp_sum(s);
            float sc = 1.0f / fmaxf(sqrtf(s), 1e-12f);
            if (type == 0) sc *= SCALING;
            vv.x *= sc; vv.y *= sc; vv.z *= sc; vv.w *= sc;
            ((float4*)base)[lane] = vv;
        }
        __syncthreads();

        // ========== Attention: 30 warps x 4 rows, aw in registers ==========
        if (w < 30) {
            const int n0 = 4 * w;
            const int rot = 4 * lane;   // (4*m)&127 == 4*(m&31) == 4*lane, j-indep
            int offs[4];
            #pragma unroll
            for (int j = 0; j < 4; j++) {
                int m = lane + 32 * j;
                offs[j] = ((m < NNEI) ? m : 0) * HD;
            }
            // --- QK^T: 4 rows share each k load, packed over h ---
            u64 acc[4][4];
            #pragma unroll
            for (int r = 0; r < 4; r++)
                #pragma unroll
                for (int j = 0; j < 4; j++) acc[r][j] = 0ull;
            #pragma unroll 1
            for (int h = 0; h < HD; h += 4) {
                ulonglong2 q0 = *(const ulonglong2*)(sq + (n0 + 0) * HD + h);
                ulonglong2 q1 = *(const ulonglong2*)(sq + (n0 + 1) * HD + h);
                ulonglong2 q2 = *(const ulonglong2*)(sq + (n0 + 2) * HD + h);
                ulonglong2 q3 = *(const ulonglong2*)(sq + (n0 + 3) * HD + h);
                #pragma unroll
                for (int j = 0; j < 4; j++) {
                    ulonglong2 kk = *(const ulonglong2*)(sk + offs[j] + (h ^ rot));
                    acc[0][j] = ffma2(q0.x, kk.x, acc[0][j]);
                    acc[0][j] = ffma2(q0.y, kk.y, acc[0][j]);
                    acc[1][j] = ffma2(q1.x, kk.x, acc[1][j]);
                    acc[1][j] = ffma2(q1.y, kk.y, acc[1][j]);
                    acc[2][j] = ffma2(q2.x, kk.x, acc[2][j]);
                    acc[2][j] = ffma2(q2.y, kk.y, acc[2][j]);
                    acc[3][j] = ffma2(q3.x, kk.x, acc[3][j]);
                    acc[3][j] = ffma2(q3.y, kk.y, acc[3][j]);
                }
            }
            // --- per-m data (after QK to limit register peak) ---
            float smk[4], rmx[4], rmy[4], rmz[4];
            #pragma unroll
            for (int j = 0; j < 4; j++) {
                int m = lane + 32 * j;
                int mc = (m < NNEI) ? m : 0;
                smk[j] = (m < NNEI) ? smask[m] : 0.0f;
                rmx[j] = sr[mc * 3]; rmy[j] = sr[mc * 3 + 1]; rmz[j] = sr[mc * 3 + 2];
            }
            // --- softmax + mask + angle -> aw registers ---
            float awr[4][4];
            #pragma unroll
            for (int r = 0; r < 4; r++) {
                int n = n0 + r;
                float lg[4]; float mx = -1e30f;
                #pragma unroll
                for (int j = 0; j < 4; j++) {
                    float s = hsum2(acc[r][j]);
                    lg[j] = (smk[j] > 0.5f) ? s : -1e30f;
                    mx = fmaxf(mx, lg[j]);
                }
                mx = warp_max(mx);
                float ex[4], ssum = 0.f;
                #pragma unroll
                for (int j = 0; j < 4; j++) { ex[j] = __expf(lg[j] - mx); ssum += ex[j]; }
                ssum = warp_sum(ssum);
                float coef = smask[n] / ssum;
                float rn0 = sr[n * 3], rn1 = sr[n * 3 + 1], rn2 = sr[n * 3 + 2];
                #pragma unroll
                for (int j = 0; j < 4; j++) {
                    float ang = rn0 * rmx[j] + rn1 * rmy[j] + rn2 * rmz[j];
                    awr[r][j] = ex[j] * coef * ang;   // 0 for masked/invalid m (ex=0)
                }
            }
            // --- AV: v loads shared by 4 rows, aw via shuffle ---
            u64 oa[4], ob[4];
            #pragma unroll
            for (int r = 0; r < 4; r++) { oa[r] = 0ull; ob[r] = 0ull; }
            #pragma unroll
            for (int j = 0; j < 4; j++) {
                const int tmax = (j < 3) ? 32 : (NNEI - 96);
                #pragma unroll 4
                for (int t = 0; t < tmax; t++) {
                    int m = 32 * j + t;
                    ulonglong2 vv = *(const ulonglong2*)(sv + m * HD + 4 * lane);
                    float a0 = __shfl_sync(0xffffffffu, awr[0][j], t);
                    float a1 = __shfl_sync(0xffffffffu, awr[1][j], t);
                    float a2 = __shfl_sync(0xffffffffu, awr[2][j], t);
                    float a3 = __shfl_sync(0xffffffffu, awr[3][j], t);
                    u64 p0 = pack2(a0, a0), p1 = pack2(a1, a1);
                    u64 p2 = pack2(a2, a2), p3 = pack2(a3, a3);
                    oa[0] = ffma2(p0, vv.x, oa[0]); ob[0] = ffma2(p0, vv.y, ob[0]);
                    oa[1] = ffma2(p1, vv.x, oa[1]); ob[1] = ffma2(p1, vv.y, ob[1]);
                    oa[2] = ffma2(p2, vv.x, oa[2]); ob[2] = ffma2(p2, vv.y, ob[2]);
                    oa[3] = ffma2(p3, vv.x, oa[3]); ob[3] = ffma2(p3, vv.y, ob[3]);
                }
            }
            #pragma unroll
            for (int r = 0; r < 4; r++) {
                ulonglong2 ov; ov.x = oa[r]; ov.y = ob[r];
                *(ulonglong2*)(sq + (n0 + r) * HD + 4 * lane) = ov;  // q <- o
            }
        }
        __syncthreads();

        // ========== Phase F: x = LN(residual + o @ out_w + out_b)  (packed over h) ==========
        const float* Ow = out_w + (size_t)l * HD * ED;
        u64 accF[4][2];
        #pragma unroll
        for (int i = 0; i < 4; i++) { accF[i][0] = 0ull; accF[i][1] = 0ull; }
        for (int hc = 0; hc < 4; hc++) {
            // stage 32 h x 64 e chunk, pair-interleaved over h
            for (int idx = tid; idx < 32 * ED; idx += NTHREADS) {
                int hl = idx >> 6, e = idx & 63;
                sbuf[(hl >> 1) * 128 + 2 * e + (hl & 1)] = Ow[(hc * 32 + hl) * ED + e];
            }
            __syncthreads();
            #pragma unroll 4
            for (int h2 = 0; h2 < 16; h2++) {
                u64 w0 = *(const u64*)(sbuf + h2 * 128 + 2 * lane);
                u64 w1 = *(const u64*)(sbuf + h2 * 128 + 64 + 2 * lane);
                #pragma unroll
                for (int i = 0; i < 4; i++) {
                    int n = w + 32 * i;
                    if (n < NNEI) {
                        u64 op = *(const u64*)(sq + n * HD + hc * 32 + 2 * h2);
                        accF[i][0] = ffma2(op, w0, accF[i][0]);
                        accF[i][1] = ffma2(op, w1, accF[i][1]);
                    }
                }
            }
            __syncthreads();
        }
        {
            float ob0 = out_b[l * ED + lane],      ob1 = out_b[l * ED + 32 + lane];
            float g0  = ln_g[l * ED + lane],       g1  = ln_g[l * ED + 32 + lane];
            float bb0 = ln_b[l * ED + lane],       bb1 = ln_b[l * ED + 32 + lane];
            #pragma unroll
            for (int i = 0; i < 4; i++) {
                int n = w + 32 * i;
                if (n < NNEI) {
                    float x0 = sx[n * ED + lane]      + hsum2(accF[i][0]) + ob0;
                    float x1 = sx[n * ED + 32 + lane] + hsum2(accF[i][1]) + ob1;
                    float mu = warp_sum(x0 + x1) * (1.0f / 64.0f);
                    float d0 = x0 - mu, d1 = x1 - mu;
                    float var = warp_sum(d0 * d0 + d1 * d1) * (1.0f / 64.0f);
                    float rs = rsqrtf(var + LN_EPS);
                    sx[n * ED + lane]      = d0 * rs * g0 + bb0;
                    sx[n * ED + 32 + lane] = d1 * rs * g1 + bb1;
                }
            }
        }
        __syncthreads();
    }

    // ---- write output ----
    float4* outp = (float4*)(out + (size_t)b * NNEI * ED);
    for (int i = tid; i < NNEI * ED / 4; i += NTHREADS) outp[i] = sx4[i];
}

extern "C" void kernel_launch(void* const* d_in, const int* in_sizes, int n_in,
                              void* d_out, int out_size) {
    const float* G     = (const float*)d_in[0];
    const int* mk      = (const int*)d_in[1];      // bool -> int32 per harness dtypes
    const float* r     = (const float*)d_in[2];
    const float* in_w  = (const float*)d_in[3];
    const float* in_b  = (const float*)d_in[4];
    const float* out_w = (const float*)d_in[5];
    const float* out_b = (const float*)d_in[6];
    const float* ln_g  = (const float*)d_in[7];
    const float* ln_b  = (const float*)d_in[8];
    float* out         = (float*)d_out;

    int B = in_sizes[0] / (NNEI * ED);

    cudaFuncSetAttribute(nwa_kernel, cudaFuncAttributeMaxDynamicSharedMemorySize,
                         SMEM_FLOATS * sizeof(float));
    nwa_kernel<<<B, NTHREADS, SMEM_FLOATS * sizeof(float)>>>(
        G, mk, r, in_w, in_b, out_w, out_b, ln_g, ln_b, out);
}